// round 1
// baseline (speedup 1.0000x reference)
#include <cuda_runtime.h>
#include <cuda_bf16.h>

#define BB   4096      // batch rows
#define SEQ  2048      // sequence length S
#define SU   2056      // u row stride (S + E)
#define OUTW 2057      // out row stride (S + AR + 1)
#define KC   128       // chunk length
#define NCH  16        // number of chunks (SEQ / KC)
#define ORD  9         // recurrence order (AR + 1)
#define EX   8         // exogenous dim

// Scratch (static device globals — no allocation in kernel_launch)
__device__ float g_H[144];            // impulse response, zero-padded to 144
__device__ float g_MT[ORD * ORD];     // MT[r*9+k] = M[k][r] (boundary state map)
__device__ float g_v[BB * NCH * ORD]; // per-chunk input vectors
__device__ float g_s[BB * NCH * ORD]; // chunk boundary states s_0..s_{NC-1}

// ---------------------------------------------------------------------------
// Kernel 1: compute impulse response H and boundary matrix M from W.
// a[0]=-W0, a[k]=W[k-1]-W[k] (k=1..7), a[8]=1+W7.
// Thread r (0..8): run recurrence from unit state e_r, c=0; final window = M column r.
// Thread 9: impulse response H[p].
// Threads 10..25: zero-pad H[128..143].
// ---------------------------------------------------------------------------
__global__ void coef_kernel(const float* __restrict__ W) {
    __shared__ float sa[ORD];
    int t = threadIdx.x;
    if (t == 0) {
        sa[0] = -W[0];
        #pragma unroll
        for (int k = 1; k < 8; k++) sa[k] = W[k - 1] - W[k];
        sa[8] = 1.0f + W[7];
    }
    __syncthreads();
    float a[ORD];
    #pragma unroll
    for (int k = 0; k < ORD; k++) a[k] = sa[k];

    if (t < ORD) {
        float w[ORD];
        #pragma unroll
        for (int k = 0; k < ORD; k++) w[k] = (k == t) ? 1.0f : 0.0f;
        for (int p = 0; p < KC; p++) {
            float z = 0.0f;
            #pragma unroll
            for (int k = 0; k < ORD; k++) z += a[k] * w[k];
            #pragma unroll
            for (int k = 0; k < ORD - 1; k++) w[k] = w[k + 1];
            w[ORD - 1] = z;
        }
        #pragma unroll
        for (int k = 0; k < ORD; k++) g_MT[t * ORD + k] = w[k];
    } else if (t == ORD) {
        float w[ORD];
        #pragma unroll
        for (int k = 0; k < ORD; k++) w[k] = 0.0f;
        for (int p = 0; p < KC; p++) {
            float z = 0.0f;
            #pragma unroll
            for (int k = 0; k < ORD; k++) z += a[k] * w[k];
            if (p == 0) z += 1.0f;
            g_H[p] = z;
            #pragma unroll
            for (int k = 0; k < ORD - 1; k++) w[k] = w[k + 1];
            w[ORD - 1] = z;
        }
    } else if (t >= 10 && t < 26) {
        g_H[KC + (t - 10)] = 0.0f;   // zero pad H[128..143]
    }
}

// ---------------------------------------------------------------------------
// Kernel 2: per (row b, chunk m) compute v[k] = sum_l H[l] * c_{K-9+k-l}
// where c_j = sum_e wu[e] * u[b, 1 + m*K + j + e], c_{j<0} := 0.
// Rolling windows cw (c values) and uw (u values) kept in registers; the
// shift is a modular index rotation resolved at compile time (unroll by 9).
// ---------------------------------------------------------------------------
__global__ void __launch_bounds__(256) vchunk_kernel(const float* __restrict__ u,
                                                     const float* __restrict__ W) {
    __shared__ float sH[144];
    int t = threadIdx.x;
    if (t < 144) sH[t] = g_H[t];
    __syncthreads();

    int task = blockIdx.x * 256 + t;
    int b = task >> 4;       // / NCH
    int m = task & 15;       // % NCH
    const float* ub = u + (size_t)b * SU + 1 + m * KC;

    float wu[EX];
    #pragma unroll
    for (int e = 0; e < EX; e++) wu[e] = __ldg(&W[8 + e]);

    // tmp[q] = ub[K-10+q], q=0..16
    float tmp[17];
    #pragma unroll
    for (int q = 0; q < 17; q++) tmp[q] = ub[KC - 10 + q];

    float cw[ORD], uw[ORD], va[ORD];
    #pragma unroll
    for (int k = 0; k < ORD; k++) {
        float acc = 0.0f;                      // cw[k] = c_{K-9+k}
        #pragma unroll
        for (int e = 0; e < EX; e++) acc += wu[e] * tmp[1 + k + e];
        cw[k] = acc;
        va[k] = 0.0f;
        uw[k] = tmp[k];                        // uw logical[q] = ub[K-10+q]
    }

    for (int l0 = 0; l0 < 135; l0 += 9) {
        #pragma unroll
        for (int s = 0; s < 9; s++) {
            int l = l0 + s;
            float hl = sH[l];
            #pragma unroll
            for (int k = 0; k < ORD; k++) va[k] += hl * cw[(k + 9 - s) % 9];
            int j = KC - 10 - l;               // next c index
            float nc = 0.0f;
            #pragma unroll
            for (int e = 0; e < EX; e++) nc += wu[e] * uw[(e + 9 - s) % 9];
            if (j < 0) nc = 0.0f;
            cw[(8 - s) % 9] = nc;              // new logical cw[0]
            int jl = j - 1; if (jl < 0) jl = 0;
            uw[(8 - s) % 9] = ub[jl];          // new logical uw[0] = ub[j-1]
        }
    }

    float* gv = g_v + (size_t)task * ORD;
    #pragma unroll
    for (int k = 0; k < ORD; k++) gv[k] = va[k];
}

// ---------------------------------------------------------------------------
// Kernel 3: sequential over NC=16 chunk boundaries per row:
// s_{m+1}[k] = sum_r M[k][r] s_m[r] + v_m[k].  Also copies y -> out[0..8].
// ---------------------------------------------------------------------------
__global__ void __launch_bounds__(256) states_kernel(const float* __restrict__ y,
                                                     float* __restrict__ out) {
    __shared__ float sMT[ORD * ORD];
    int t = threadIdx.x;
    if (t < ORD * ORD) sMT[t] = g_MT[t];
    __syncthreads();

    int b = blockIdx.x * 256 + t;
    float s[ORD];
    #pragma unroll
    for (int k = 0; k < ORD; k++) {
        s[k] = y[(size_t)b * ORD + k];
        out[(size_t)b * OUTW + k] = s[k];
    }
    float* gs = g_s + (size_t)b * NCH * ORD;
    #pragma unroll
    for (int k = 0; k < ORD; k++) gs[k] = s[k];

    for (int m = 0; m < NCH - 1; m++) {
        const float* vv = g_v + ((size_t)b * NCH + m) * ORD;
        float ns[ORD];
        #pragma unroll
        for (int k = 0; k < ORD; k++) ns[k] = vv[k];
        #pragma unroll
        for (int r = 0; r < ORD; r++) {
            float sr = s[r];
            #pragma unroll
            for (int k = 0; k < ORD; k++) ns[k] += sMT[r * ORD + k] * sr;
        }
        #pragma unroll
        for (int k = 0; k < ORD; k++) { s[k] = ns[k]; gs[(m + 1) * ORD + k] = s[k]; }
    }
}

// ---------------------------------------------------------------------------
// Kernel 4: per (row, chunk) replay the exact local recurrence from the
// boundary state; c computed on the fly from u. Rotation via unroll-9.
// ---------------------------------------------------------------------------
__global__ void __launch_bounds__(256) out_kernel(const float* __restrict__ u,
                                                  const float* __restrict__ W,
                                                  float* __restrict__ out) {
    int t = threadIdx.x;
    int task = blockIdx.x * 256 + t;
    int b = task >> 4;
    int m = task & 15;
    const float* ub = u + (size_t)b * SU + 1 + m * KC;
    float* ob = out + (size_t)b * OUTW + ORD + m * KC;

    float a[ORD], wu[EX];
    a[0] = -__ldg(&W[0]);
    #pragma unroll
    for (int k = 1; k < 8; k++) a[k] = __ldg(&W[k - 1]) - __ldg(&W[k]);
    a[8] = 1.0f + __ldg(&W[7]);
    #pragma unroll
    for (int e = 0; e < EX; e++) wu[e] = __ldg(&W[8 + e]);

    float w[ORD], uw[ORD];
    const float* gs = g_s + (size_t)task * ORD;
    #pragma unroll
    for (int k = 0; k < ORD; k++) { w[k] = gs[k]; uw[k] = ub[k]; }

    for (int j0 = 0; j0 < 135; j0 += 9) {
        #pragma unroll
        for (int s = 0; s < 9; s++) {
            int j = j0 + s;
            if (j < KC) {
                float c = 0.0f;
                #pragma unroll
                for (int e = 0; e < EX; e++) c += wu[e] * uw[(e + s) % 9];
                float x = c;
                #pragma unroll
                for (int k = 0; k < ORD; k++) x += a[k] * w[(k + s) % 9];
                ob[j] = x;
                w[s] = x;                       // new logical w[8]
                int jn = j + 9; if (jn > KC + 6) jn = KC + 6;  // clamp (value unused)
                uw[s] = ub[jn];                 // new logical uw[8] = ub[j+9]
            }
        }
    }
}

// ---------------------------------------------------------------------------
extern "C" void kernel_launch(void* const* d_in, const int* in_sizes, int n_in,
                              void* d_out, int out_size) {
    const float* y = (const float*)d_in[0];
    const float* u = (const float*)d_in[1];
    const float* W = (const float*)d_in[2];
    // Defensive mapping by element count (y=36864, u=8421376, W=16)
    for (int i = 0; i < n_in; i++) {
        if (in_sizes[i] == BB * ORD)      y = (const float*)d_in[i];
        else if (in_sizes[i] == BB * SU)  u = (const float*)d_in[i];
        else if (in_sizes[i] == 16)       W = (const float*)d_in[i];
    }
    float* out = (float*)d_out;

    coef_kernel<<<1, 32>>>(W);
    vchunk_kernel<<<(BB * NCH) / 256, 256>>>(u, W);
    states_kernel<<<BB / 256, 256>>>(y, out);
    out_kernel<<<(BB * NCH) / 256, 256>>>(u, W, out);
}

// round 2
// speedup vs baseline: 1.5829x; 1.5829x over previous
#include <cuda_runtime.h>
#include <cuda_bf16.h>

#define BB   4096      // batch rows
#define SEQ  2048      // sequence length S
#define SU   2056      // u row stride (S + E)
#define OUTW 2057      // out row stride (S + AR + 1)
#define KC   64        // chunk length
#define NCH  32        // chunks per row (SEQ / KC)
#define ORD  9         // recurrence order (AR + 1)
#define EX   8         // exogenous dim
#define NT   (BB * NCH)

// Static device scratch (no allocations in kernel_launch)
__device__ float g_Phi[KC * ORD];    // Phi[j][r]: response at step j to unit state e_r
__device__ float g_MT[ORD * ORD];    // MT[r*9+k] = (A^K)[k][r]
__device__ float g_v[NT * ORD];      // layout [m][b][9]: zero-state final windows
__device__ float g_s[NT * ORD];      // layout [m][b][9]: true boundary states
__device__ float g_x[BB * SEQ];      // zero-state outputs, row-major (aligned scratch)

// ---------------------------------------------------------------------------
// Kernel 1: from W build the a-coefs, run K steps from each unit state e_r
// to get Phi (per-step response) and M = A^K (final window), r = 0..8.
// ---------------------------------------------------------------------------
__global__ void coef_kernel(const float* __restrict__ W) {
    int t = threadIdx.x;
    float a[ORD];
    a[0] = -W[0];
    #pragma unroll
    for (int k = 1; k < 8; k++) a[k] = W[k - 1] - W[k];
    a[8] = 1.0f + W[7];

    if (t < ORD) {
        float w[ORD];
        #pragma unroll
        for (int k = 0; k < ORD; k++) w[k] = (k == t) ? 1.0f : 0.0f;
        for (int p = 0; p < KC; p++) {
            float z = 0.0f;
            #pragma unroll
            for (int k = 0; k < ORD; k++) z += a[k] * w[k];
            #pragma unroll
            for (int k = 0; k < ORD - 1; k++) w[k] = w[k + 1];
            w[ORD - 1] = z;
            g_Phi[p * ORD + t] = z;
        }
        #pragma unroll
        for (int k = 0; k < ORD; k++) g_MT[t * ORD + k] = w[k];
    }
}

// ---------------------------------------------------------------------------
// Kernel 2 (phase A): per (chunk m, row b) run the recurrence from the ZERO
// window with inputs c_j = sum_e W[8+e]*u[b, 1 + m*K + j + e].
// Fully unrolled (all %9 / %4 indices compile-time). u read via aligned
// LDG.128 (1 per 4 steps); x0 written via aligned STG.128 into g_x.
// Final 9-window -> g_v (coalesced layout [m][b][9]).
// ---------------------------------------------------------------------------
__global__ void __launch_bounds__(256) phaseA_kernel(const float* __restrict__ u,
                                                     const float* __restrict__ W) {
    int task = blockIdx.x * 256 + threadIdx.x;   // task = m*BB + b
    int b = task & (BB - 1);
    int m = task >> 12;
    const float* ub = u + (size_t)b * SU + 1 + m * KC;
    float* gx = g_x + (size_t)b * SEQ + m * KC;

    float a[ORD], wu[EX];
    a[0] = -__ldg(&W[0]);
    #pragma unroll
    for (int k = 1; k < 8; k++) a[k] = __ldg(&W[k - 1]) - __ldg(&W[k]);
    a[8] = 1.0f + __ldg(&W[7]);
    #pragma unroll
    for (int e = 0; e < EX; e++) wu[e] = __ldg(&W[8 + e]);

    // uv[i] = ub[i], i = 0..70.  ub+3 is 16B-aligned (row offset 1+m*64+3 ≡ 0 mod 4).
    float uv[KC + 7];
    uv[0] = ub[0]; uv[1] = ub[1]; uv[2] = ub[2];
    {
        float4 q0 = *(const float4*)(ub + 3);
        uv[3] = q0.x; uv[4] = q0.y; uv[5] = q0.z; uv[6] = q0.w;
        float4 q1 = *(const float4*)(ub + 7);
        uv[7] = q1.x; uv[8] = q1.y; uv[9] = q1.z; uv[10] = q1.w;
    }

    float w[ORD];
    #pragma unroll
    for (int k = 0; k < ORD; k++) w[k] = 0.0f;

    float xb[4];
    #pragma unroll
    for (int j = 0; j < KC; j++) {
        // Prefetch the quad first needed 4 steps from now
        if ((j & 3) == 0 && j <= KC - 8) {
            float4 q = *(const float4*)(ub + 11 + j);
            uv[j + 11] = q.x; uv[j + 12] = q.y; uv[j + 13] = q.z; uv[j + 14] = q.w;
        }
        // c_j (tree-reduced)
        float e0 = wu[0] * uv[j]     + wu[1] * uv[j + 1];
        float e1 = wu[2] * uv[j + 2] + wu[3] * uv[j + 3];
        float e2 = wu[4] * uv[j + 4] + wu[5] * uv[j + 5];
        float e3 = wu[6] * uv[j + 6] + wu[7] * uv[j + 7];
        float c  = (e0 + e1) + (e2 + e3);
        // x_j: state terms tree-reduced, newest-state term last (4-cyc cross chain)
        float s0 = c + a[0] * w[(0 + j) % 9];
        float s1 = a[1] * w[(1 + j) % 9] + a[2] * w[(2 + j) % 9];
        float s2 = a[3] * w[(3 + j) % 9] + a[4] * w[(4 + j) % 9];
        float s3 = a[5] * w[(5 + j) % 9] + a[6] * w[(6 + j) % 9];
        float x  = ((s0 + s1) + (s2 + s3)) + a[7] * w[(7 + j) % 9];
        x = fmaf(a[8], w[(8 + j) % 9], x);

        w[j % 9] = x;
        xb[j & 3] = x;
        if ((j & 3) == 3)
            *(float4*)(gx + (j - 3)) = make_float4(xb[0], xb[1], xb[2], xb[3]);
    }

    // Final 9-window in logical order: logical k -> physical (k + KC) % 9
    float* gv = g_v + (size_t)task * ORD;
    #pragma unroll
    for (int k = 0; k < ORD; k++) gv[k] = w[(k + KC) % 9];
}

// ---------------------------------------------------------------------------
// Kernel 3: per-row serial chain over NCH=32 chunk boundaries:
// s_{m+1} = M s_m + v_m.  Warp = 32 consecutive b, so g_v/g_s [m][b][9]
// loads/stores are coalesced.  Also writes out[0..8] = y.
// ---------------------------------------------------------------------------
__global__ void __launch_bounds__(256) states_kernel(const float* __restrict__ y,
                                                     float* __restrict__ out) {
    __shared__ float sMT[ORD * ORD];
    int t = threadIdx.x;
    if (t < ORD * ORD) sMT[t] = g_MT[t];
    __syncthreads();

    int b = blockIdx.x * 256 + t;
    float s[ORD];
    #pragma unroll
    for (int k = 0; k < ORD; k++) {
        s[k] = y[(size_t)b * ORD + k];
        out[(size_t)b * OUTW + k] = s[k];
        g_s[(size_t)b * ORD + k] = s[k];          // m = 0 slot: (0*BB + b)*9
    }

    for (int m = 0; m < NCH - 1; m++) {
        const float* vv = g_v + ((size_t)m * BB + b) * ORD;
        float ns[ORD];
        #pragma unroll
        for (int k = 0; k < ORD; k++) ns[k] = vv[k];
        #pragma unroll
        for (int r = 0; r < ORD; r++) {
            float sr = s[r];
            #pragma unroll
            for (int k = 0; k < ORD; k++) ns[k] += sMT[r * ORD + k] * sr;
        }
        float* gs = g_s + ((size_t)(m + 1) * BB + b) * ORD;
        #pragma unroll
        for (int k = 0; k < ORD; k++) { s[k] = ns[k]; gs[k] = s[k]; }
    }
}

// ---------------------------------------------------------------------------
// Kernel 4 (phase C): out[b, 9+i] = g_x[b, i] + Phi_j · s_m, one thread per
// output element.  g_x read coalesced, out write coalesced, Phi from smem
// (stride-9 lanes -> conflict-free), s broadcast via L1.
// ---------------------------------------------------------------------------
__global__ void __launch_bounds__(256) phaseC_kernel(float* __restrict__ out) {
    __shared__ float sPhi[KC * ORD];
    int t = threadIdx.x;
    #pragma unroll
    for (int i = t; i < KC * ORD; i += 256) sPhi[i] = g_Phi[i];
    __syncthreads();

    int tid = blockIdx.x * 256 + t;
    int b = tid >> 11;          // / SEQ
    int r = tid & (SEQ - 1);
    int m = r >> 6;             // / KC
    int j = r & (KC - 1);

    const float* sp = g_s + ((size_t)m * BB + b) * ORD;
    const float* ph = sPhi + j * ORD;

    float acc = g_x[(size_t)b * SEQ + r];
    float p0 = ph[0] * __ldg(&sp[0]) + ph[1] * __ldg(&sp[1]);
    float p1 = ph[2] * __ldg(&sp[2]) + ph[3] * __ldg(&sp[3]);
    float p2 = ph[4] * __ldg(&sp[4]) + ph[5] * __ldg(&sp[5]);
    float p3 = ph[6] * __ldg(&sp[6]) + ph[7] * __ldg(&sp[7]);
    float p4 = ph[8] * __ldg(&sp[8]);
    acc += ((p0 + p1) + (p2 + p3)) + p4;

    out[(size_t)b * OUTW + ORD + r] = acc;
}

// ---------------------------------------------------------------------------
extern "C" void kernel_launch(void* const* d_in, const int* in_sizes, int n_in,
                              void* d_out, int out_size) {
    const float* y = (const float*)d_in[0];
    const float* u = (const float*)d_in[1];
    const float* W = (const float*)d_in[2];
    for (int i = 0; i < n_in; i++) {
        if (in_sizes[i] == BB * ORD)      y = (const float*)d_in[i];
        else if (in_sizes[i] == BB * SU)  u = (const float*)d_in[i];
        else if (in_sizes[i] == 16)       W = (const float*)d_in[i];
    }
    float* out = (float*)d_out;

    coef_kernel<<<1, 32>>>(W);
    phaseA_kernel<<<NT / 256, 256>>>(u, W);
    states_kernel<<<BB / 256, 256>>>(y, out);
    phaseC_kernel<<<(BB * SEQ) / 256, 256>>>(out);
}

// round 3
// speedup vs baseline: 2.0073x; 1.2681x over previous
#include <cuda_runtime.h>
#include <cuda_bf16.h>

#define BB   4096      // batch rows
#define SEQ  2048      // sequence length S
#define SU   2056      // u row stride (S + E)
#define OUTW 2057      // out row stride (S + AR + 1)
#define KC   64        // chunk length
#define NCH  32        // chunks per row (SEQ / KC)
#define ORD  9         // recurrence order (AR + 1)
#define EX   8         // exogenous dim

// Static device scratch — all bulk arrays are b-fastest (coalesced for lane=b)
__device__ float g_MT[ORD * ORD];          // MT[r*9+k] = (A^K)[k][r]
__device__ float g_c[SEQ * BB];            // c[t][b] = sum_e W[8+e]*u[b][1+t+e]
__device__ float g_v[NCH * ORD * BB];      // [m][k][b] zero-state final windows
__device__ float g_s[NCH * ORD * BB];      // [m][k][b] true boundary states

// ---------------------------------------------------------------------------
// Kernel 1: boundary matrix M = A^K from W (a0=-W0, ak=W[k-1]-W[k], a8=1+W7)
// ---------------------------------------------------------------------------
__global__ void coef_kernel(const float* __restrict__ W) {
    int t = threadIdx.x;
    float a[ORD];
    a[0] = -W[0];
    #pragma unroll
    for (int k = 1; k < 8; k++) a[k] = W[k - 1] - W[k];
    a[8] = 1.0f + W[7];

    if (t < ORD) {
        float w[ORD];
        #pragma unroll
        for (int k = 0; k < ORD; k++) w[k] = (k == t) ? 1.0f : 0.0f;
        for (int p = 0; p < KC; p++) {
            float z = 0.0f;
            #pragma unroll
            for (int k = 0; k < ORD; k++) z += a[k] * w[k];
            #pragma unroll
            for (int k = 0; k < ORD - 1; k++) w[k] = w[k + 1];
            w[ORD - 1] = z;
        }
        #pragma unroll
        for (int k = 0; k < ORD; k++) g_MT[t * ORD + k] = w[k];
    }
}

// ---------------------------------------------------------------------------
// Kernel 2: c[t][b] via smem tile transpose. Block = 64 t x 32 b.
// u read coalesced along rows; c written coalesced along b.
// ---------------------------------------------------------------------------
__global__ void __launch_bounds__(256) c_kernel(const float* __restrict__ u,
                                                const float* __restrict__ W) {
    __shared__ float su[32][73];   // 32 b-rows x 71 cols (padded: 73 odd)
    int tm = blockIdx.x & 31;      // t-tile (SEQ/64)
    int bb = blockIdx.x >> 5;      // b-tile (BB/32)
    int t0 = tm * KC, b0 = bb * 32;
    int lane = threadIdx.x & 31, wr = threadIdx.x >> 5;

    float wu[EX];
    #pragma unroll
    for (int e = 0; e < EX; e++) wu[e] = __ldg(&W[8 + e]);

    // load u[b0+r][1+t0+cc], cc = 0..70
    #pragma unroll
    for (int rr = 0; rr < 4; rr++) {
        int r = wr * 4 + rr;
        const float* ur = u + (size_t)(b0 + r) * SU + 1 + t0;
        #pragma unroll
        for (int ci = 0; ci < 3; ci++) {
            int cc = lane + ci * 32;
            if (cc < 71) su[r][cc] = ur[cc];
        }
    }
    __syncthreads();

    // c[t0+tp][b0+lane] = sum_e wu[e]*su[lane][tp+e]; smem stride 73 conflict-free
    #pragma unroll
    for (int q = 0; q < 8; q++) {
        int tp = wr + q * 8;
        float a0 = wu[0] * su[lane][tp]     + wu[1] * su[lane][tp + 1];
        float a1 = wu[2] * su[lane][tp + 2] + wu[3] * su[lane][tp + 3];
        float a2 = wu[4] * su[lane][tp + 4] + wu[5] * su[lane][tp + 5];
        float a3 = wu[6] * su[lane][tp + 6] + wu[7] * su[lane][tp + 7];
        g_c[(size_t)(t0 + tp) * BB + b0 + lane] = (a0 + a1) + (a2 + a3);
    }
}

// ---------------------------------------------------------------------------
// Kernel 3 (pass1): zero-state recurrence per (m, b); lanes = consecutive b.
// Reads c coalesced; writes only the final 9-window to g_v[m][k][b].
// ---------------------------------------------------------------------------
__global__ void __launch_bounds__(256) pass1_kernel(const float* __restrict__ W) {
    int task = blockIdx.x * 256 + threadIdx.x;   // task = m*BB + b
    int b = task & (BB - 1);
    int m = task >> 12;

    float a[ORD];
    a[0] = -__ldg(&W[0]);
    #pragma unroll
    for (int k = 1; k < 8; k++) a[k] = __ldg(&W[k - 1]) - __ldg(&W[k]);
    a[8] = 1.0f + __ldg(&W[7]);

    const float* cb = g_c + (size_t)(m * KC) * BB + b;

    float w[ORD];
    #pragma unroll
    for (int k = 0; k < ORD; k++) w[k] = 0.0f;

    #pragma unroll
    for (int j = 0; j < KC; j++) {
        float c = cb[(size_t)j * BB];
        float s0 = c + a[0] * w[(0 + j) % 9];
        float s1 = a[1] * w[(1 + j) % 9] + a[2] * w[(2 + j) % 9];
        float s2 = a[3] * w[(3 + j) % 9] + a[4] * w[(4 + j) % 9];
        float s3 = a[5] * w[(5 + j) % 9] + a[6] * w[(6 + j) % 9];
        float x  = ((s0 + s1) + (s2 + s3)) + a[7] * w[(7 + j) % 9];
        x = fmaf(a[8], w[(8 + j) % 9], x);
        w[j % 9] = x;
    }

    // logical final-window k -> physical (k + KC) % 9
    float* gv = g_v + ((size_t)m * ORD) * BB + b;
    #pragma unroll
    for (int k = 0; k < ORD; k++) gv[(size_t)k * BB] = w[(k + KC) % 9];
}

// ---------------------------------------------------------------------------
// Kernel 4: per-row serial chain over NCH boundaries: s_{m+1} = M s_m + v_m.
// All g_v/g_s traffic coalesced ([m][k][b]). Also writes out[b][0..8] = y.
// ---------------------------------------------------------------------------
__global__ void __launch_bounds__(256) states_kernel(const float* __restrict__ y,
                                                     float* __restrict__ out) {
    __shared__ float sMT[ORD * ORD];
    int t = threadIdx.x;
    if (t < ORD * ORD) sMT[t] = g_MT[t];
    __syncthreads();

    int b = blockIdx.x * 256 + t;
    float s[ORD];
    #pragma unroll
    for (int k = 0; k < ORD; k++) {
        s[k] = y[(size_t)b * ORD + k];
        out[(size_t)b * OUTW + k] = s[k];
        g_s[(size_t)k * BB + b] = s[k];            // m = 0
    }

    for (int m = 0; m < NCH - 1; m++) {
        const float* vv = g_v + ((size_t)m * ORD) * BB + b;
        float ns[ORD];
        #pragma unroll
        for (int k = 0; k < ORD; k++) ns[k] = vv[(size_t)k * BB];
        #pragma unroll
        for (int r = 0; r < ORD; r++) {
            float sr = s[r];
            #pragma unroll
            for (int k = 0; k < ORD; k++) ns[k] += sMT[r * ORD + k] * sr;
        }
        float* gs = g_s + ((size_t)(m + 1) * ORD) * BB + b;
        #pragma unroll
        for (int k = 0; k < ORD; k++) { s[k] = ns[k]; gs[(size_t)k * BB] = s[k]; }
    }
}

// ---------------------------------------------------------------------------
// Kernel 5 (pass2): replay recurrence from the true boundary state; buffer 16
// steps in smem and write out in b-row-coalesced 64B segments.
// Block = one chunk m x 256 consecutive b.
// ---------------------------------------------------------------------------
__global__ void __launch_bounds__(256) pass2_kernel(const float* __restrict__ W,
                                                    float* __restrict__ out) {
    __shared__ float sb[16][257];
    int tid = threadIdx.x;
    int m  = blockIdx.x >> 4;
    int b0 = (blockIdx.x & 15) * 256;
    int b  = b0 + tid;

    float a[ORD];
    a[0] = -__ldg(&W[0]);
    #pragma unroll
    for (int k = 1; k < 8; k++) a[k] = __ldg(&W[k - 1]) - __ldg(&W[k]);
    a[8] = 1.0f + __ldg(&W[7]);

    float w[ORD];
    const float* gs = g_s + ((size_t)m * ORD) * BB + b;
    #pragma unroll
    for (int k = 0; k < ORD; k++) w[k] = gs[(size_t)k * BB];

    const float* cb = g_c + (size_t)(m * KC) * BB + b;
    int ocol0 = ORD + m * KC;

    #pragma unroll
    for (int j = 0; j < KC; j++) {
        float c = cb[(size_t)j * BB];
        float s0 = c + a[0] * w[(0 + j) % 9];
        float s1 = a[1] * w[(1 + j) % 9] + a[2] * w[(2 + j) % 9];
        float s2 = a[3] * w[(3 + j) % 9] + a[4] * w[(4 + j) % 9];
        float s3 = a[5] * w[(5 + j) % 9] + a[6] * w[(6 + j) % 9];
        float x  = ((s0 + s1) + (s2 + s3)) + a[7] * w[(7 + j) % 9];
        x = fmaf(a[8], w[(8 + j) % 9], x);
        w[j % 9] = x;

        sb[j & 15][tid] = x;
        if ((j & 15) == 15) {
            __syncthreads();
            int jj = j & ~15;
            #pragma unroll
            for (int q = 0; q < 16; q++) {
                int e  = q * 256 + tid;
                int tp = e & 15;
                int bp = e >> 4;
                out[(size_t)(b0 + bp) * OUTW + ocol0 + jj + tp] = sb[tp][bp];
            }
            __syncthreads();
        }
    }
}

// ---------------------------------------------------------------------------
extern "C" void kernel_launch(void* const* d_in, const int* in_sizes, int n_in,
                              void* d_out, int out_size) {
    const float* y = (const float*)d_in[0];
    const float* u = (const float*)d_in[1];
    const float* W = (const float*)d_in[2];
    for (int i = 0; i < n_in; i++) {
        if (in_sizes[i] == BB * ORD)      y = (const float*)d_in[i];
        else if (in_sizes[i] == BB * SU)  u = (const float*)d_in[i];
        else if (in_sizes[i] == 16)       W = (const float*)d_in[i];
    }
    float* out = (float*)d_out;

    coef_kernel<<<1, 32>>>(W);
    c_kernel<<<(SEQ / KC) * (BB / 32), 256>>>(u, W);      // 4096 blocks
    pass1_kernel<<<(NCH * BB) / 256, 256>>>(W);
    states_kernel<<<BB / 256, 256>>>(y, out);
    pass2_kernel<<<NCH * (BB / 256), 256>>>(W, out);
}

// round 4
// speedup vs baseline: 2.5274x; 1.2591x over previous
#include <cuda_runtime.h>
#include <cuda_bf16.h>

#define BB   4096      // batch rows
#define SEQ  2048      // sequence length S
#define SU   2056      // u row stride (S + E)
#define OUTW 2057      // out row stride (S + AR + 1)
#define KC   64        // chunk length
#define NCH  32        // chunks per row (SEQ / KC)
#define ORD  9         // recurrence order (AR + 1)
#define EX   8         // exogenous dim

// Static device scratch — all bulk arrays are b-fastest (coalesced for lane=b)
__device__ float g_MT[ORD * ORD];          // MT[r*9+k] = (A^K)[k][r]
__device__ float g_c[SEQ * BB];            // c[t][b]
__device__ float g_v[NCH * ORD * BB];      // [m][k][b] zero-state final windows
__device__ float g_s[NCH * ORD * BB];      // [m][k][b] true boundary states

// ---------------------------------------------------------------------------
// Kernel 1: boundary matrix M = A^K from W (a0=-W0, ak=W[k-1]-W[k], a8=1+W7)
// ---------------------------------------------------------------------------
__global__ void coef_kernel(const float* __restrict__ W) {
    int t = threadIdx.x;
    float a[ORD];
    a[0] = -W[0];
    #pragma unroll
    for (int k = 1; k < 8; k++) a[k] = W[k - 1] - W[k];
    a[8] = 1.0f + W[7];

    if (t < ORD) {
        float w[ORD];
        #pragma unroll
        for (int k = 0; k < ORD; k++) w[k] = (k == t) ? 1.0f : 0.0f;
        for (int p = 0; p < KC; p++) {
            float z = 0.0f;
            #pragma unroll
            for (int k = 0; k < ORD; k++) z += a[k] * w[k];
            #pragma unroll
            for (int k = 0; k < ORD - 1; k++) w[k] = w[k + 1];
            w[ORD - 1] = z;
        }
        #pragma unroll
        for (int k = 0; k < ORD; k++) g_MT[t * ORD + k] = w[k];
    }
}

// ---------------------------------------------------------------------------
// Kernel 2 (cv): c tile via smem transpose -> g_c AND smem; then warp 0 runs
// the zero-state recurrence for its 32 b-lanes straight from smem -> g_v.
// Block = chunk m (64 t) x 32 b, 256 threads. (pass1 fused away)
// ---------------------------------------------------------------------------
__global__ void __launch_bounds__(256) cv_kernel(const float* __restrict__ u,
                                                 const float* __restrict__ W) {
    __shared__ float su[32][73];   // 32 b-rows x 71 u-values (pad 73)
    __shared__ float sc[KC][33];   // c tile, [t][b] (pad 33)
    int tm = blockIdx.x & 31;      // chunk index m
    int bb = blockIdx.x >> 5;      // b-tile
    int t0 = tm * KC, b0 = bb * 32;
    int lane = threadIdx.x & 31, wr = threadIdx.x >> 5;

    float wu[EX];
    #pragma unroll
    for (int e = 0; e < EX; e++) wu[e] = __ldg(&W[8 + e]);

    // load u[b0+r][1+t0+cc], cc = 0..70 (coalesced along rows)
    #pragma unroll
    for (int rr = 0; rr < 4; rr++) {
        int r = wr * 4 + rr;
        const float* ur = u + (size_t)(b0 + r) * SU + 1 + t0;
        #pragma unroll
        for (int ci = 0; ci < 3; ci++) {
            int cc = lane + ci * 32;
            if (cc < 71) su[r][cc] = ur[cc];
        }
    }
    __syncthreads();

    // c[t0+tp][b0+lane]; write both g_c (coalesced) and sc
    #pragma unroll
    for (int q = 0; q < 8; q++) {
        int tp = wr + q * 8;
        float a0 = wu[0] * su[lane][tp]     + wu[1] * su[lane][tp + 1];
        float a1 = wu[2] * su[lane][tp + 2] + wu[3] * su[lane][tp + 3];
        float a2 = wu[4] * su[lane][tp + 4] + wu[5] * su[lane][tp + 5];
        float a3 = wu[6] * su[lane][tp + 6] + wu[7] * su[lane][tp + 7];
        float cv = (a0 + a1) + (a2 + a3);
        g_c[(size_t)(t0 + tp) * BB + b0 + lane] = cv;
        sc[tp][lane] = cv;
    }
    __syncthreads();

    // warp 0: zero-state recurrence, 64 steps from smem c
    if (threadIdx.x < 32) {
        float a[ORD];
        a[0] = -__ldg(&W[0]);
        #pragma unroll
        for (int k = 1; k < 8; k++) a[k] = __ldg(&W[k - 1]) - __ldg(&W[k]);
        a[8] = 1.0f + __ldg(&W[7]);

        float w[ORD];
        #pragma unroll
        for (int k = 0; k < ORD; k++) w[k] = 0.0f;

        #pragma unroll
        for (int j = 0; j < KC; j++) {
            float c = sc[j][lane];
            float s0 = c + a[0] * w[(0 + j) % 9];
            float s1 = a[1] * w[(1 + j) % 9] + a[2] * w[(2 + j) % 9];
            float s2 = a[3] * w[(3 + j) % 9] + a[4] * w[(4 + j) % 9];
            float s3 = a[5] * w[(5 + j) % 9] + a[6] * w[(6 + j) % 9];
            float x  = ((s0 + s1) + (s2 + s3)) + a[7] * w[(7 + j) % 9];
            x = fmaf(a[8], w[(8 + j) % 9], x);
            w[j % 9] = x;
        }

        float* gv = g_v + ((size_t)tm * ORD) * BB + b0 + lane;
        #pragma unroll
        for (int k = 0; k < ORD; k++) gv[(size_t)k * BB] = w[(k + KC) % 9];
    }
}

// ---------------------------------------------------------------------------
// Kernel 3: boundary-state chain, 128 blocks x 32 threads (lane = b).
// M held in registers (broadcast loads), v double-buffer prefetched 2 deep
// so the 31-iteration chain is FMA-issue bound, not L2-latency bound.
// ---------------------------------------------------------------------------
__global__ void __launch_bounds__(32) states_kernel(const float* __restrict__ y,
                                                    float* __restrict__ out) {
    int lane = threadIdx.x;
    int b = blockIdx.x * 32 + lane;

    float MT[ORD * ORD];
    #pragma unroll
    for (int i = 0; i < ORD * ORD; i++) MT[i] = g_MT[i];   // broadcast

    float s[ORD];
    #pragma unroll
    for (int k = 0; k < ORD; k++) {
        s[k] = y[(size_t)b * ORD + k];
        out[(size_t)b * OUTW + k] = s[k];
        g_s[(size_t)k * BB + b] = s[k];                    // m = 0
    }

    float va[ORD], vb[ORD];
    #pragma unroll
    for (int k = 0; k < ORD; k++) va[k] = g_v[(size_t)k * BB + b];            // m=0
    #pragma unroll
    for (int k = 0; k < ORD; k++) vb[k] = g_v[((size_t)ORD + k) * BB + b];    // m=1

    #pragma unroll
    for (int m = 0; m < NCH - 1; m++) {
        float ns[ORD];
        #pragma unroll
        for (int k = 0; k < ORD; k++) ns[k] = va[k];
        #pragma unroll
        for (int k = 0; k < ORD; k++) va[k] = vb[k];       // renamed after unroll
        if (m + 2 <= NCH - 2) {
            const float* gv = g_v + ((size_t)(m + 2) * ORD) * BB + b;
            #pragma unroll
            for (int k = 0; k < ORD; k++) vb[k] = gv[(size_t)k * BB];
        }
        #pragma unroll
        for (int r = 0; r < ORD; r++) {
            float sr = s[r];
            #pragma unroll
            for (int k = 0; k < ORD; k++) ns[k] += MT[r * ORD + k] * sr;
        }
        float* gs = g_s + ((size_t)(m + 1) * ORD) * BB + b;
        #pragma unroll
        for (int k = 0; k < ORD; k++) { s[k] = ns[k]; gs[(size_t)k * BB] = s[k]; }
    }
}

// ---------------------------------------------------------------------------
// Kernel 4 (pass2): replay recurrence from true boundary state; smem-buffer
// 16 steps and write out rows in coalesced 64B segments.
// ---------------------------------------------------------------------------
__global__ void __launch_bounds__(256) pass2_kernel(const float* __restrict__ W,
                                                    float* __restrict__ out) {
    __shared__ float sb[16][257];
    int tid = threadIdx.x;
    int m  = blockIdx.x >> 4;
    int b0 = (blockIdx.x & 15) * 256;
    int b  = b0 + tid;

    float a[ORD];
    a[0] = -__ldg(&W[0]);
    #pragma unroll
    for (int k = 1; k < 8; k++) a[k] = __ldg(&W[k - 1]) - __ldg(&W[k]);
    a[8] = 1.0f + __ldg(&W[7]);

    float w[ORD];
    const float* gs = g_s + ((size_t)m * ORD) * BB + b;
    #pragma unroll
    for (int k = 0; k < ORD; k++) w[k] = gs[(size_t)k * BB];

    const float* cb = g_c + (size_t)(m * KC) * BB + b;
    int ocol0 = ORD + m * KC;

    #pragma unroll
    for (int j = 0; j < KC; j++) {
        float c = cb[(size_t)j * BB];
        float s0 = c + a[0] * w[(0 + j) % 9];
        float s1 = a[1] * w[(1 + j) % 9] + a[2] * w[(2 + j) % 9];
        float s2 = a[3] * w[(3 + j) % 9] + a[4] * w[(4 + j) % 9];
        float s3 = a[5] * w[(5 + j) % 9] + a[6] * w[(6 + j) % 9];
        float x  = ((s0 + s1) + (s2 + s3)) + a[7] * w[(7 + j) % 9];
        x = fmaf(a[8], w[(8 + j) % 9], x);
        w[j % 9] = x;

        sb[j & 15][tid] = x;
        if ((j & 15) == 15) {
            __syncthreads();
            int jj = j & ~15;
            #pragma unroll
            for (int q = 0; q < 16; q++) {
                int e  = q * 256 + tid;
                int tp = e & 15;
                int bp = e >> 4;
                out[(size_t)(b0 + bp) * OUTW + ocol0 + jj + tp] = sb[tp][bp];
            }
            __syncthreads();
        }
    }
}

// ---------------------------------------------------------------------------
extern "C" void kernel_launch(void* const* d_in, const int* in_sizes, int n_in,
                              void* d_out, int out_size) {
    const float* y = (const float*)d_in[0];
    const float* u = (const float*)d_in[1];
    const float* W = (const float*)d_in[2];
    for (int i = 0; i < n_in; i++) {
        if (in_sizes[i] == BB * ORD)      y = (const float*)d_in[i];
        else if (in_sizes[i] == BB * SU)  u = (const float*)d_in[i];
        else if (in_sizes[i] == 16)       W = (const float*)d_in[i];
    }
    float* out = (float*)d_out;

    coef_kernel<<<1, 32>>>(W);
    cv_kernel<<<(SEQ / KC) * (BB / 32), 256>>>(u, W);   // 4096 blocks
    states_kernel<<<BB / 32, 32>>>(y, out);             // 128 blocks
    pass2_kernel<<<NCH * (BB / 256), 256>>>(W, out);
}

// round 5
// speedup vs baseline: 3.2687x; 1.2933x over previous
#include <cuda_runtime.h>
#include <cuda_bf16.h>

#define BB   4096      // batch rows
#define SEQ  2048      // sequence length S
#define SU   2056      // u row stride (S + E)
#define OUTW 2057      // out row stride (S + AR + 1)
#define KC   64        // chunk length
#define NCH  32        // chunks per row (SEQ / KC)
#define ORD  9         // recurrence order (AR + 1)
#define EX   8         // exogenous dim
#define BT   128       // b-rows per block in the two big passes

// Static device scratch (b-fastest layouts, coalesced for lane = b)
__device__ float g_v[NCH * ORD * BB];      // [m][k][b] zero-state final windows
__device__ float g_s[NCH * ORD * BB];      // [m][k][b] true boundary states

// Common: load a-coefs from W
__device__ __forceinline__ void load_a(const float* __restrict__ W, float* a) {
    a[0] = -__ldg(&W[0]);
    #pragma unroll
    for (int k = 1; k < 8; k++) a[k] = __ldg(&W[k - 1]) - __ldg(&W[k]);
    a[8] = 1.0f + __ldg(&W[7]);
}

// ---------------------------------------------------------------------------
// Kernel 1 (cv): per (chunk m, 128-row b-tile): stage u tile in smem, every
// thread runs the ZERO-state recurrence for its row with a rolling u window
// (1 LDS + 17 FMA per step), emit only the final 9-window to g_v[m][k][b].
// ---------------------------------------------------------------------------
__global__ void __launch_bounds__(BT) cv_kernel(const float* __restrict__ u,
                                                const float* __restrict__ W) {
    __shared__ float su[BT][73];           // stride 73: gcd(73,32)=1, conflict-free
    int m  = blockIdx.x >> 5;
    int b0 = (blockIdx.x & 31) * BT;
    int tid = threadIdx.x;
    int lane = tid & 31, wr = tid >> 5;

    // coalesced tile load: u[b0+r][1 + m*64 + cc], cc = 0..70
    #pragma unroll
    for (int r = wr; r < BT; r += 4) {
        const float* ur = u + (size_t)(b0 + r) * SU + 1 + m * KC;
        #pragma unroll
        for (int ci = 0; ci < 3; ci++) {
            int cc = lane + ci * 32;
            if (cc < 71) su[r][cc] = ur[cc];
        }
    }
    __syncthreads();

    float a[ORD], wu[EX];
    load_a(W, a);
    #pragma unroll
    for (int e = 0; e < EX; e++) wu[e] = __ldg(&W[8 + e]);

    float w[ORD], uw[ORD];
    #pragma unroll
    for (int k = 0; k < ORD; k++) { w[k] = 0.0f; uw[k] = su[tid][k]; }

    #pragma unroll
    for (int j = 0; j < KC; j++) {
        float e0 = wu[0] * uw[(0 + j) % 9] + wu[1] * uw[(1 + j) % 9];
        float e1 = wu[2] * uw[(2 + j) % 9] + wu[3] * uw[(3 + j) % 9];
        float e2 = wu[4] * uw[(4 + j) % 9] + wu[5] * uw[(5 + j) % 9];
        float e3 = wu[6] * uw[(6 + j) % 9] + wu[7] * uw[(7 + j) % 9];
        float c  = (e0 + e1) + (e2 + e3);
        if (j + 9 <= 70) uw[j % 9] = su[tid][j + 9];   // refill logical slot 8

        float s0 = c + a[0] * w[(0 + j) % 9];
        float s1 = a[1] * w[(1 + j) % 9] + a[2] * w[(2 + j) % 9];
        float s2 = a[3] * w[(3 + j) % 9] + a[4] * w[(4 + j) % 9];
        float s3 = a[5] * w[(5 + j) % 9] + a[6] * w[(6 + j) % 9];
        float x  = ((s0 + s1) + (s2 + s3)) + a[7] * w[(7 + j) % 9];
        x = fmaf(a[8], w[(8 + j) % 9], x);
        w[j % 9] = x;
    }

    float* gv = g_v + ((size_t)m * ORD) * BB + b0 + tid;
    #pragma unroll
    for (int k = 0; k < ORD; k++) gv[(size_t)k * BB] = w[(k + KC) % 9];
}

// ---------------------------------------------------------------------------
// Kernel 2 (states, coef fused): each block computes M = A^K in registers
// (lanes 0..8 run unit-state recurrences, 81 shfl broadcasts), then runs the
// 31-step boundary chain with 2-deep v prefetch. Writes out[b][0..8] = y.
// ---------------------------------------------------------------------------
__global__ void __launch_bounds__(32) states_kernel(const float* __restrict__ W,
                                                    const float* __restrict__ y,
                                                    float* __restrict__ out) {
    int lane = threadIdx.x;
    int b = blockIdx.x * 32 + lane;

    float a[ORD];
    load_a(W, a);

    // unit-state recurrence: lane r (<9) produces column r of A^K
    float w[ORD];
    #pragma unroll
    for (int k = 0; k < ORD; k++) w[k] = (k == lane) ? 1.0f : 0.0f;
    #pragma unroll
    for (int p = 0; p < KC; p++) {
        float z = 0.0f;
        #pragma unroll
        for (int k = 0; k < ORD; k++) z += a[k] * w[(k + p) % 9];
        w[p % 9] = z;
    }
    // MT[r*9+k] = (A^K)[k][r]; logical k -> phys (k + KC)%9
    float MT[ORD * ORD];
    #pragma unroll
    for (int r = 0; r < ORD; r++)
        #pragma unroll
        for (int k = 0; k < ORD; k++)
            MT[r * ORD + k] = __shfl_sync(0xffffffffu, w[(k + KC) % 9], r);

    float s[ORD];
    #pragma unroll
    for (int k = 0; k < ORD; k++) {
        s[k] = y[(size_t)b * ORD + k];
        out[(size_t)b * OUTW + k] = s[k];
        g_s[(size_t)k * BB + b] = s[k];                // m = 0
    }

    float va[ORD], vb[ORD];
    #pragma unroll
    for (int k = 0; k < ORD; k++) va[k] = g_v[(size_t)k * BB + b];
    #pragma unroll
    for (int k = 0; k < ORD; k++) vb[k] = g_v[((size_t)ORD + k) * BB + b];

    #pragma unroll
    for (int m = 0; m < NCH - 1; m++) {
        float ns[ORD];
        #pragma unroll
        for (int k = 0; k < ORD; k++) ns[k] = va[k];
        #pragma unroll
        for (int k = 0; k < ORD; k++) va[k] = vb[k];
        if (m + 2 <= NCH - 2) {
            const float* gv = g_v + ((size_t)(m + 2) * ORD) * BB + b;
            #pragma unroll
            for (int k = 0; k < ORD; k++) vb[k] = gv[(size_t)k * BB];
        }
        #pragma unroll
        for (int r = 0; r < ORD; r++) {
            float sr = s[r];
            #pragma unroll
            for (int k = 0; k < ORD; k++) ns[k] += MT[r * ORD + k] * sr;
        }
        float* gs = g_s + ((size_t)(m + 1) * ORD) * BB + b;
        #pragma unroll
        for (int k = 0; k < ORD; k++) { s[k] = ns[k]; gs[(size_t)k * BB] = s[k]; }
    }
}

// ---------------------------------------------------------------------------
// Kernel 3 (pass2): same u-tile + rolling-window recurrence, but starting
// from the TRUE boundary state; stages 16 steps in smem and writes out rows
// in coalesced 64B segments.
// ---------------------------------------------------------------------------
__global__ void __launch_bounds__(BT) pass2_kernel(const float* __restrict__ u,
                                                   const float* __restrict__ W,
                                                   float* __restrict__ out) {
    __shared__ float su[BT][73];
    __shared__ float sb[16][BT + 1];
    int m  = blockIdx.x >> 5;
    int b0 = (blockIdx.x & 31) * BT;
    int tid = threadIdx.x;
    int lane = tid & 31, wr = tid >> 5;

    #pragma unroll
    for (int r = wr; r < BT; r += 4) {
        const float* ur = u + (size_t)(b0 + r) * SU + 1 + m * KC;
        #pragma unroll
        for (int ci = 0; ci < 3; ci++) {
            int cc = lane + ci * 32;
            if (cc < 71) su[r][cc] = ur[cc];
        }
    }
    __syncthreads();

    float a[ORD], wu[EX];
    load_a(W, a);
    #pragma unroll
    for (int e = 0; e < EX; e++) wu[e] = __ldg(&W[8 + e]);

    float w[ORD], uw[ORD];
    const float* gs = g_s + ((size_t)m * ORD) * BB + b0 + tid;
    #pragma unroll
    for (int k = 0; k < ORD; k++) { w[k] = gs[(size_t)k * BB]; uw[k] = su[tid][k]; }

    int ocol0 = ORD + m * KC;

    #pragma unroll
    for (int j = 0; j < KC; j++) {
        float e0 = wu[0] * uw[(0 + j) % 9] + wu[1] * uw[(1 + j) % 9];
        float e1 = wu[2] * uw[(2 + j) % 9] + wu[3] * uw[(3 + j) % 9];
        float e2 = wu[4] * uw[(4 + j) % 9] + wu[5] * uw[(5 + j) % 9];
        float e3 = wu[6] * uw[(6 + j) % 9] + wu[7] * uw[(7 + j) % 9];
        float c  = (e0 + e1) + (e2 + e3);
        if (j + 9 <= 70) uw[j % 9] = su[tid][j + 9];

        float s0 = c + a[0] * w[(0 + j) % 9];
        float s1 = a[1] * w[(1 + j) % 9] + a[2] * w[(2 + j) % 9];
        float s2 = a[3] * w[(3 + j) % 9] + a[4] * w[(4 + j) % 9];
        float s3 = a[5] * w[(5 + j) % 9] + a[6] * w[(6 + j) % 9];
        float x  = ((s0 + s1) + (s2 + s3)) + a[7] * w[(7 + j) % 9];
        x = fmaf(a[8], w[(8 + j) % 9], x);
        w[j % 9] = x;

        sb[j & 15][tid] = x;
        if ((j & 15) == 15) {
            __syncthreads();
            int jj = j & ~15;
            #pragma unroll
            for (int q = 0; q < 16; q++) {
                int e  = q * BT + tid;
                int tp = e & 15;
                int bp = e >> 4;
                out[(size_t)(b0 + bp) * OUTW + ocol0 + jj + tp] = sb[tp][bp];
            }
            __syncthreads();
        }
    }
}

// ---------------------------------------------------------------------------
extern "C" void kernel_launch(void* const* d_in, const int* in_sizes, int n_in,
                              void* d_out, int out_size) {
    const float* y = (const float*)d_in[0];
    const float* u = (const float*)d_in[1];
    const float* W = (const float*)d_in[2];
    for (int i = 0; i < n_in; i++) {
        if (in_sizes[i] == BB * ORD)      y = (const float*)d_in[i];
        else if (in_sizes[i] == BB * SU)  u = (const float*)d_in[i];
        else if (in_sizes[i] == 16)       W = (const float*)d_in[i];
    }
    float* out = (float*)d_out;

    cv_kernel<<<NCH * (BB / BT), BT>>>(u, W);       // 1024 blocks x 128
    states_kernel<<<BB / 32, 32>>>(W, y, out);      // 128 blocks x 32
    pass2_kernel<<<NCH * (BB / BT), BT>>>(u, W, out);
}